// round 5
// baseline (speedup 1.0000x reference)
#include <cuda_runtime.h>
#include <math.h>
#include <stdint.h>

#define B 64
#define T 1024
#define E 512
#define R 1024
#define A 128
#define F 32
#define KS 31
#define PADC 15

#define TM 128          // t-tile of energy GEMM
#define KC 32           // k-chunk
#define SA 36           // skA stride (conflict-free A frags)
#define SB 136          // swB stride (conflict-free B frags)
#define SZA (TM * SA)   // 4608 floats per A stage
#define SZB (KC * SB)   // 4352 floats per B stage
#define SMEM_BYTES ((2 * SZA + 2 * SZB) * 4)   // 71680 B

// scratch (allocation-free rule: __device__ globals)
__device__ float  g_q[B * A];                         // 32 KB
__device__ float4 g_feat4[(size_t)B * T * F / 4];     // 8 MB, [B][T][F]
__device__ float  g_e[B * T];                         // 256 KB
__device__ float4 g_ctxpart4[B * 16 * E / 4];         // 2 MB
__device__ int    g_maskmode;                         // 0=u8, 1=i32, 2=f32

// ---------------------------------------------------------------------------
// helpers
// ---------------------------------------------------------------------------
__device__ __forceinline__ void cp16(float* dst_smem, const float* src) {
    uint32_t d = (uint32_t)__cvta_generic_to_shared(dst_smem);
    asm volatile("cp.async.ca.shared.global [%0], [%1], 16;" :: "r"(d), "l"(src));
}
__device__ __forceinline__ uint32_t ld_tf32(const float* p) {
    uint32_t u;
    asm("cvt.rna.tf32.f32 %0, %1;" : "=r"(u) : "f"(*p));
    return u;
}
__device__ __forceinline__ void mma_tf32(float& c0, float& c1, float& c2, float& c3,
                                         uint32_t a0, uint32_t a1, uint32_t a2, uint32_t a3,
                                         uint32_t b0, uint32_t b1) {
    asm volatile(
        "mma.sync.aligned.m16n8k8.row.col.f32.tf32.tf32.f32 "
        "{%0,%1,%2,%3}, {%4,%5,%6,%7}, {%8,%9}, {%0,%1,%2,%3};"
        : "+f"(c0), "+f"(c1), "+f"(c2), "+f"(c3)
        : "r"(a0), "r"(a1), "r"(a2), "r"(a3), "r"(b0), "r"(b1));
}

// ---------------------------------------------------------------------------
// 0) sniff mask dtype (first 64 KB reinterpreted as u32 — safe for all dtypes)
// ---------------------------------------------------------------------------
__global__ void mask_mode_kernel(const unsigned int* __restrict__ w) {
    __shared__ int s_not_int, s_not_flt;
    int tid = threadIdx.x;
    if (tid == 0) { s_not_int = 0; s_not_flt = 0; }
    __syncthreads();
    int not_int = 0, not_flt = 0;
    for (int i = tid; i < (B * T) / 4; i += blockDim.x) {
        unsigned int x = w[i];
        if (x > 1u) not_int = 1;
        if (x != 0u && x != 0x3F800000u) not_flt = 1;
    }
    if (not_int) atomicOr(&s_not_int, 1);
    if (not_flt) atomicOr(&s_not_flt, 1);
    __syncthreads();
    if (tid == 0)
        g_maskmode = (!s_not_int) ? 1 : ((!s_not_flt) ? 2 : 0);
}

__device__ __forceinline__ bool read_mask(const void* m, int idx, int mode) {
    if (mode == 1) return ((const int*)m)[idx] != 0;
    if (mode == 2) return ((const float*)m)[idx] != 0.f;
    return ((const unsigned char*)m)[idx] != 0;
}

// ---------------------------------------------------------------------------
// 1) q = query @ Wq  [B,A]; split-R over 8 groups + smem reduce
// ---------------------------------------------------------------------------
__global__ void qproj_kernel(const float* __restrict__ query,
                             const float* __restrict__ Wq) {
    int b = blockIdx.x;
    int tid = threadIdx.x;          // 1024
    int g = tid >> 7, a = tid & 127;
    __shared__ float sred[8][128];
    const float* qb = query + (size_t)b * R + g * 128;
    const float* wp = Wq + (size_t)(g * 128) * A + a;
    float acc = 0.f;
    #pragma unroll 8
    for (int r = 0; r < 128; r++)
        acc += qb[r] * wp[(size_t)r * A];
    sred[g][a] = acc;
    __syncthreads();
    if (g == 0) {
        float s = 0.f;
        #pragma unroll
        for (int k = 0; k < 8; k++) s += sred[k][a];
        g_q[b * A + a] = s;
    }
}

// ---------------------------------------------------------------------------
// 2) feat = BN(relu(conv1d(cat)))  -> g_feat [B][T][F]
// ---------------------------------------------------------------------------
__global__ void loc_kernel(const float* __restrict__ cat,
                           const float* __restrict__ conv_w,
                           const float* __restrict__ gamma,
                           const float* __restrict__ beta,
                           const float* __restrict__ mean,
                           const float* __restrict__ var) {
    int b  = blockIdx.y;
    int t0 = blockIdx.x * 128;
    int j  = threadIdx.x;           // 128 threads

    __shared__ float xs[2][158];
    __shared__ float cw[F * 2 * KS];
    __shared__ float feat[F][129];

    for (int idx = j; idx < 2 * 158; idx += 128) {
        int ch = idx / 158, p = idx % 158;
        int tt = t0 - PADC + p;
        xs[ch][p] = (tt >= 0 && tt < T) ? cat[(size_t)b * 2 * T + (size_t)ch * T + tt] : 0.f;
    }
    for (int idx = j; idx < F * 2 * KS; idx += 128)
        cw[idx] = conv_w[idx];
    __syncthreads();

    for (int f = 0; f < F; f++) {
        float acc = 0.f;
        #pragma unroll
        for (int ch = 0; ch < 2; ch++)
            #pragma unroll
            for (int k = 0; k < KS; k++)
                acc += xs[ch][j + k] * cw[(f * 2 + ch) * KS + k];
        float val = fmaxf(acc, 0.f);
        val = (val - mean[f]) * (rsqrtf(var[f] + 1e-5f) * gamma[f]) + beta[f];
        feat[f][j] = val;
    }
    __syncthreads();

    #pragma unroll
    for (int i = 0; i < 8; i++) {
        int li = j + i * 128;       // 0..1023 float4s
        int t = li >> 3, fg = li & 7;
        float4 v4;
        v4.x = feat[fg * 4 + 0][t];
        v4.y = feat[fg * 4 + 1][t];
        v4.z = feat[fg * 4 + 2][t];
        v4.w = feat[fg * 4 + 3][t];
        g_feat4[((size_t)b * T + t0 + t) * (F / 4) + fg] = v4;
    }
}

// ---------------------------------------------------------------------------
// 3) energy: tf32 MMA GEMM 128x128x(512+32) with 2-stage cp.async pipeline
// ---------------------------------------------------------------------------
__device__ __forceinline__ void load_chunk(int chunk, int tid, float* sA, float* sB,
                                           const float* keyb, const float* featb,
                                           const float* Wk, const float* Wloc) {
    if (chunk < 16) {
        int e0 = chunk * KC;
        #pragma unroll
        for (int i = 0; i < 4; i++) {
            int li = tid + i * 256;
            int row = li >> 3, cg = li & 7;
            cp16(sA + row * SA + cg * 4, keyb + (size_t)row * E + e0 + cg * 4);
        }
        #pragma unroll
        for (int i = 0; i < 4; i++) {
            int li = tid + i * 256;
            int row = li >> 5, cg = li & 31;
            cp16(sB + row * SB + cg * 4, Wk + (size_t)(e0 + row) * A + cg * 4);
        }
    } else {
        #pragma unroll
        for (int i = 0; i < 4; i++) {
            int li = tid + i * 256;
            int row = li >> 3, cg = li & 7;
            cp16(sA + row * SA + cg * 4, featb + (size_t)row * F + cg * 4);
        }
        #pragma unroll
        for (int i = 0; i < 4; i++) {
            int li = tid + i * 256;
            int row = li >> 5, cg = li & 31;
            cp16(sB + row * SB + cg * 4, Wloc + (size_t)row * A + cg * 4);
        }
    }
    asm volatile("cp.async.commit_group;");
}

__global__ void __launch_bounds__(256, 2)
energy_kernel(const float* __restrict__ key,
              const float* __restrict__ Wk,
              const float* __restrict__ Wloc,
              const void* __restrict__ mask,
              const float* __restrict__ v) {
    int b  = blockIdx.y;
    int t0 = blockIdx.x * TM;
    int tid = threadIdx.x;
    int lane = tid & 31;
    int wid  = tid >> 5;
    int warp_m = wid >> 2;          // 0..1 (64 rows each)
    int warp_n = wid & 3;           // 0..3 (32 cols each)

    extern __shared__ float dsm[];
    float* stA[2] = {dsm, dsm + SZA};
    float* stB[2] = {dsm + 2 * SZA, dsm + 2 * SZA + SZB};

    float acc[4][4][4];
    #pragma unroll
    for (int i = 0; i < 4; i++)
        #pragma unroll
        for (int j = 0; j < 4; j++)
            #pragma unroll
            for (int r = 0; r < 4; r++) acc[i][j][r] = 0.f;

    const float* keyb  = key + (size_t)b * T * E + (size_t)t0 * E;
    const float* featb = (const float*)g_feat4 + ((size_t)b * T + t0) * F;

    load_chunk(0, tid, stA[0], stB[0], keyb, featb, Wk, Wloc);

    for (int c = 0; c < 17; c++) {
        float* sA = stA[c & 1];
        float* sB = stB[c & 1];
        if (c < 16) {
            load_chunk(c + 1, tid, stA[(c + 1) & 1], stB[(c + 1) & 1],
                       keyb, featb, Wk, Wloc);
            asm volatile("cp.async.wait_group 1;");
        } else {
            asm volatile("cp.async.wait_group 0;");
        }
        __syncthreads();

        #pragma unroll
        for (int ks = 0; ks < 4; ks++) {
            int k0 = ks * 8;
            uint32_t af[4][4];
            #pragma unroll
            for (int mf = 0; mf < 4; mf++) {
                int rbase = warp_m * 64 + mf * 16 + (lane >> 2);
                int kcol = k0 + (lane & 3);
                af[mf][0] = ld_tf32(sA + rbase * SA + kcol);
                af[mf][1] = ld_tf32(sA + (rbase + 8) * SA + kcol);
                af[mf][2] = ld_tf32(sA + rbase * SA + kcol + 4);
                af[mf][3] = ld_tf32(sA + (rbase + 8) * SA + kcol + 4);
            }
            uint32_t bf[4][2];
            #pragma unroll
            for (int nf = 0; nf < 4; nf++) {
                int col = warp_n * 32 + nf * 8 + (lane >> 2);
                int krow = k0 + (lane & 3);
                bf[nf][0] = ld_tf32(sB + krow * SB + col);
                bf[nf][1] = ld_tf32(sB + (krow + 4) * SB + col);
            }
            #pragma unroll
            for (int mf = 0; mf < 4; mf++)
                #pragma unroll
                for (int nf = 0; nf < 4; nf++)
                    mma_tf32(acc[mf][nf][0], acc[mf][nf][1],
                             acc[mf][nf][2], acc[mf][nf][3],
                             af[mf][0], af[mf][1], af[mf][2], af[mf][3],
                             bf[nf][0], bf[nf][1]);
        }
        __syncthreads();
    }

    // ---- epilogue: e[t] = sum_a v[a] * tanh(q[a] + S[t,a]) ----
    float part[4][2];
    #pragma unroll
    for (int mf = 0; mf < 4; mf++) { part[mf][0] = 0.f; part[mf][1] = 0.f; }

    #pragma unroll
    for (int nf = 0; nf < 4; nf++) {
        int c0 = warp_n * 32 + nf * 8 + 2 * (lane & 3);
        float qv0 = g_q[b * A + c0],     qv1 = g_q[b * A + c0 + 1];
        float vv0 = v[c0],               vv1 = v[c0 + 1];
        #pragma unroll
        for (int mf = 0; mf < 4; mf++) {
            part[mf][0] += vv0 * tanhf(qv0 + acc[mf][nf][0])
                         + vv1 * tanhf(qv1 + acc[mf][nf][1]);
            part[mf][1] += vv0 * tanhf(qv0 + acc[mf][nf][2])
                         + vv1 * tanhf(qv1 + acc[mf][nf][3]);
        }
    }

    float* red = dsm;                // reuse: [128][5]
    #pragma unroll
    for (int mf = 0; mf < 4; mf++) {
        #pragma unroll
        for (int r = 0; r < 2; r++) {
            float p = part[mf][r];
            p += __shfl_xor_sync(0xFFFFFFFFu, p, 1);
            p += __shfl_xor_sync(0xFFFFFFFFu, p, 2);
            if ((lane & 3) == 0) {
                int row = warp_m * 64 + mf * 16 + (lane >> 2) + r * 8;
                red[row * 5 + warp_n] = p;
            }
        }
    }
    __syncthreads();

    if (tid < TM) {
        float s = red[tid * 5 + 0] + red[tid * 5 + 1]
                + red[tid * 5 + 2] + red[tid * 5 + 3];
        int t = t0 + tid;
        int mode = g_maskmode;
        g_e[b * T + t] = read_mask(mask, b * T + t, mode) ? -INFINITY : s;
    }
}

// ---------------------------------------------------------------------------
// 4) softmax over T per batch -> weights into d_out[B*E ..]
// ---------------------------------------------------------------------------
__global__ void softmax_kernel(float* __restrict__ out) {
    int b = blockIdx.x;
    int tid = threadIdx.x;          // 256 threads, 4 elems each
    __shared__ float sred[256];

    float vals[4];
    float m = -INFINITY;
    #pragma unroll
    for (int i = 0; i < 4; i++) {
        vals[i] = g_e[b * T + tid + i * 256];
        m = fmaxf(m, vals[i]);
    }
    sred[tid] = m; __syncthreads();
    for (int s = 128; s > 0; s >>= 1) {
        if (tid < s) sred[tid] = fmaxf(sred[tid], sred[tid + s]);
        __syncthreads();
    }
    m = sred[0]; __syncthreads();

    float sum = 0.f;
    #pragma unroll
    for (int i = 0; i < 4; i++) {
        vals[i] = expf(vals[i] - m);
        sum += vals[i];
    }
    sred[tid] = sum; __syncthreads();
    for (int s = 128; s > 0; s >>= 1) {
        if (tid < s) sred[tid] += sred[tid + s];
        __syncthreads();
    }
    float inv = 1.f / sred[0];

    float* w = out + B * E + (size_t)b * T;
    #pragma unroll
    for (int i = 0; i < 4; i++) w[tid + i * 256] = vals[i] * inv;
}

// ---------------------------------------------------------------------------
// 5) context: 16 T-chunks, 2-way t-split per block (256 thr), then reduce
// ---------------------------------------------------------------------------
__global__ void ctx_part_kernel(const float* __restrict__ key,
                                const float* __restrict__ out) {
    int b = blockIdx.y;
    int c = blockIdx.x;             // 0..15, 64 t each
    int tid = threadIdx.x;          // 256
    int e4 = tid & 127, h = tid >> 7;
    const float* w = out + B * E + (size_t)b * T + c * 64 + h * 32;
    const float4* kp = (const float4*)(key + (size_t)b * T * E)
                     + (size_t)(c * 64 + h * 32) * (E / 4) + e4;
    float4 acc = make_float4(0.f, 0.f, 0.f, 0.f);
    #pragma unroll 8
    for (int t = 0; t < 32; t++) {
        float4 k4 = kp[(size_t)t * (E / 4)];
        float wt = w[t];
        acc.x += wt * k4.x; acc.y += wt * k4.y;
        acc.z += wt * k4.z; acc.w += wt * k4.w;
    }
    __shared__ float4 sred[256];
    sred[tid] = acc;
    __syncthreads();
    if (h == 0) {
        float4 o = sred[tid];
        float4 p = sred[tid + 128];
        o.x += p.x; o.y += p.y; o.z += p.z; o.w += p.w;
        g_ctxpart4[(b * 16 + c) * (E / 4) + e4] = o;
    }
}

__global__ void ctx_reduce_kernel(float* __restrict__ out) {
    int b = blockIdx.x;
    int e4 = threadIdx.x;           // 128
    float4 s = make_float4(0.f, 0.f, 0.f, 0.f);
    #pragma unroll
    for (int c = 0; c < 16; c++) {
        float4 p = g_ctxpart4[(b * 16 + c) * (E / 4) + e4];
        s.x += p.x; s.y += p.y; s.z += p.z; s.w += p.w;
    }
    float* o = out + (size_t)b * E + e4 * 4;
    o[0] = s.x; o[1] = s.y; o[2] = s.z; o[3] = s.w;
}

// ---------------------------------------------------------------------------
extern "C" void kernel_launch(void* const* d_in, const int* in_sizes, int n_in,
                              void* d_out, int out_size) {
    const float* query  = (const float*)d_in[0];
    const float* key    = (const float*)d_in[1];
    const float* cat    = (const float*)d_in[2];
    const void*  mask   = (const void*)d_in[3];
    const float* Wq     = (const float*)d_in[4];
    const float* Wk     = (const float*)d_in[5];
    const float* conv_w = (const float*)d_in[6];
    const float* gamma  = (const float*)d_in[7];
    const float* beta   = (const float*)d_in[8];
    const float* mean   = (const float*)d_in[9];
    const float* var    = (const float*)d_in[10];
    const float* Wloc   = (const float*)d_in[11];
    const float* v      = (const float*)d_in[12];
    float* out = (float*)d_out;

    cudaFuncSetAttribute(energy_kernel,
                         cudaFuncAttributeMaxDynamicSharedMemorySize, SMEM_BYTES);

    mask_mode_kernel<<<1, 256>>>((const unsigned int*)mask);
    qproj_kernel<<<B, 1024>>>(query, Wq);
    loc_kernel<<<dim3(T / 128, B), 128>>>(cat, conv_w, gamma, beta, mean, var);
    energy_kernel<<<dim3(T / TM, B), 256, SMEM_BYTES>>>(key, Wk, Wloc, mask, v);
    softmax_kernel<<<B, 256>>>(out);
    ctx_part_kernel<<<dim3(16, B), 256>>>(key, out);
    ctx_reduce_kernel<<<B, 128>>>(out);
}

// round 6
// speedup vs baseline: 1.0403x; 1.0403x over previous
#include <cuda_runtime.h>
#include <math.h>
#include <stdint.h>

#define B 64
#define T 1024
#define E 512
#define R 1024
#define A 128
#define F 32
#define KS 31
#define PADC 15

#define TM 128          // t-tile of energy GEMM
#define KC 32           // k-chunk
#define NCHUNK 17       // 16 key chunks + 1 feat/Wloc chunk
#define SA 36           // sA stride (conflict-free A frags)
#define SB 136          // sB stride (conflict-free B frags)
#define SZA (TM * SA)   // 4608 floats
#define SZB (KC * SB)   // 4352 floats
#define SMEM_BYTES ((SZA + 2 * SZB) * 4)   // 53248 B

// scratch (allocation-free rule: __device__ globals)
__device__ float  g_q[B * A];                         // 32 KB
__device__ float4 g_feat4[(size_t)B * T * F / 4];     // 8 MB, [B][T][F]
__device__ float  g_e[B * T];                         // 256 KB
__device__ float4 g_ctxpart4[B * 16 * E / 4];         // 2 MB
__device__ float  g_wb[(E + F) * A];                  // 278 KB tf32-rounded Wk;Wloc
__device__ int    g_maskmode;                         // 0=u8, 1=i32, 2=f32

// ---------------------------------------------------------------------------
// helpers
// ---------------------------------------------------------------------------
__device__ __forceinline__ void cp16(float* dst_smem, const float* src) {
    uint32_t d = (uint32_t)__cvta_generic_to_shared(dst_smem);
    asm volatile("cp.async.ca.shared.global [%0], [%1], 16;" :: "r"(d), "l"(src));
}
__device__ __forceinline__ float cvt_tf32(float x) {
    uint32_t u;
    asm("cvt.rna.tf32.f32 %0, %1;" : "=r"(u) : "f"(x));
    return __uint_as_float(u);
}
__device__ __forceinline__ void mma_tf32(float& c0, float& c1, float& c2, float& c3,
                                         uint32_t a0, uint32_t a1, uint32_t a2, uint32_t a3,
                                         uint32_t b0, uint32_t b1) {
    asm volatile(
        "mma.sync.aligned.m16n8k8.row.col.f32.tf32.tf32.f32 "
        "{%0,%1,%2,%3}, {%4,%5,%6,%7}, {%8,%9}, {%0,%1,%2,%3};"
        : "+f"(c0), "+f"(c1), "+f"(c2), "+f"(c3)
        : "r"(a0), "r"(a1), "r"(a2), "r"(a3), "r"(b0), "r"(b1));
}

// ---------------------------------------------------------------------------
// 0a) sniff mask dtype
// ---------------------------------------------------------------------------
__global__ void mask_mode_kernel(const unsigned int* __restrict__ w) {
    __shared__ int s_not_int, s_not_flt;
    int tid = threadIdx.x;
    if (tid == 0) { s_not_int = 0; s_not_flt = 0; }
    __syncthreads();
    int not_int = 0, not_flt = 0;
    for (int i = tid; i < (B * T) / 4; i += blockDim.x) {
        unsigned int x = w[i];
        if (x > 1u) not_int = 1;
        if (x != 0u && x != 0x3F800000u) not_flt = 1;
    }
    if (not_int) atomicOr(&s_not_int, 1);
    if (not_flt) atomicOr(&s_not_flt, 1);
    __syncthreads();
    if (tid == 0)
        g_maskmode = (!s_not_int) ? 1 : ((!s_not_flt) ? 2 : 0);
}

__device__ __forceinline__ bool read_mask(const void* m, int idx, int mode) {
    if (mode == 1) return ((const int*)m)[idx] != 0;
    if (mode == 2) return ((const float*)m)[idx] != 0.f;
    return ((const unsigned char*)m)[idx] != 0;
}

// ---------------------------------------------------------------------------
// 0b) pre-round Wk (512x128) ++ Wloc (32x128) to tf32 into g_wb
// ---------------------------------------------------------------------------
__global__ void wb_kernel(const float* __restrict__ Wk,
                          const float* __restrict__ Wloc) {
    int i = blockIdx.x * 1024 + threadIdx.x;
    if (i < E * A)
        g_wb[i] = cvt_tf32(Wk[i]);
    else if (i < (E + F) * A)
        g_wb[i] = cvt_tf32(Wloc[i - E * A]);
}

// ---------------------------------------------------------------------------
// 1) q = query @ Wq  [B,A]; split-R over 8 groups + smem reduce
// ---------------------------------------------------------------------------
__global__ void qproj_kernel(const float* __restrict__ query,
                             const float* __restrict__ Wq) {
    int b = blockIdx.x;
    int tid = threadIdx.x;          // 1024
    int g = tid >> 7, a = tid & 127;
    __shared__ float sred[8][128];
    const float* qb = query + (size_t)b * R + g * 128;
    const float* wp = Wq + (size_t)(g * 128) * A + a;
    float acc = 0.f;
    #pragma unroll 8
    for (int r = 0; r < 128; r++)
        acc += qb[r] * wp[(size_t)r * A];
    sred[g][a] = acc;
    __syncthreads();
    if (g == 0) {
        float s = 0.f;
        #pragma unroll
        for (int k = 0; k < 8; k++) s += sred[k][a];
        g_q[b * A + a] = s;
    }
}

// ---------------------------------------------------------------------------
// 2) feat = BN(relu(conv1d(cat)))  -> g_feat [B][T][F]  (tf32-rounded)
// ---------------------------------------------------------------------------
__global__ void loc_kernel(const float* __restrict__ cat,
                           const float* __restrict__ conv_w,
                           const float* __restrict__ gamma,
                           const float* __restrict__ beta,
                           const float* __restrict__ mean,
                           const float* __restrict__ var) {
    int b  = blockIdx.y;
    int t0 = blockIdx.x * 128;
    int j  = threadIdx.x;           // 128 threads

    __shared__ float xs[2][158];
    __shared__ float cw[F * 2 * KS];
    __shared__ float feat[F][129];

    for (int idx = j; idx < 2 * 158; idx += 128) {
        int ch = idx / 158, p = idx % 158;
        int tt = t0 - PADC + p;
        xs[ch][p] = (tt >= 0 && tt < T) ? cat[(size_t)b * 2 * T + (size_t)ch * T + tt] : 0.f;
    }
    for (int idx = j; idx < F * 2 * KS; idx += 128)
        cw[idx] = conv_w[idx];
    __syncthreads();

    for (int f = 0; f < F; f++) {
        float acc = 0.f;
        #pragma unroll
        for (int ch = 0; ch < 2; ch++)
            #pragma unroll
            for (int k = 0; k < KS; k++)
                acc += xs[ch][j + k] * cw[(f * 2 + ch) * KS + k];
        float val = fmaxf(acc, 0.f);
        val = (val - mean[f]) * (rsqrtf(var[f] + 1e-5f) * gamma[f]) + beta[f];
        feat[f][j] = cvt_tf32(val);          // pre-round: energy A path copies raw
    }
    __syncthreads();

    #pragma unroll
    for (int i = 0; i < 8; i++) {
        int li = j + i * 128;       // 0..1023 float4s
        int t = li >> 3, fg = li & 7;
        float4 v4;
        v4.x = feat[fg * 4 + 0][t];
        v4.y = feat[fg * 4 + 1][t];
        v4.z = feat[fg * 4 + 2][t];
        v4.w = feat[fg * 4 + 3][t];
        g_feat4[((size_t)b * T + t0 + t) * (F / 4) + fg] = v4;
    }
}

// ---------------------------------------------------------------------------
// 3) energy: tf32 MMA GEMM 128x128x(512+32)
//    A: register-prefetch double buffer (cvt at STS), B: cp.async 2-stage
// ---------------------------------------------------------------------------
__global__ void __launch_bounds__(256, 2)
energy_kernel(const float* __restrict__ key,
              const void* __restrict__ mask,
              const float* __restrict__ v) {
    int b  = blockIdx.y;
    int t0 = blockIdx.x * TM;
    int tid = threadIdx.x;
    int lane = tid & 31;
    int wid  = tid >> 5;
    int warp_m = wid >> 2;          // 0..1 (64 rows each)
    int warp_n = wid & 3;           // 0..3 (32 cols each)

    extern __shared__ float dsm[];
    float* sA = dsm;                          // [128][36]
    float* stB[2] = {dsm + SZA, dsm + SZA + SZB};

    float acc[4][4][4];
    #pragma unroll
    for (int i = 0; i < 4; i++)
        #pragma unroll
        for (int j = 0; j < 4; j++)
            #pragma unroll
            for (int r = 0; r < 4; r++) acc[i][j][r] = 0.f;

    const float* keyb  = key + (size_t)b * T * E + (size_t)t0 * E;
    const float* featb = (const float*)g_feat4 + ((size_t)b * T + t0) * F;

    // per-thread A-tile indices (row/col fixed across chunks)
    int rowA[4], cgA[4];
    #pragma unroll
    for (int i = 0; i < 4; i++) {
        int li = tid + i * 256;
        rowA[i] = li >> 3;
        cgA[i]  = (li & 7) * 4;
    }
    int rowB = (tid + 0) >> 5;      // B tile: 2 rows per thread (li>>5 for i=0,1... )

    // ---- prologue: chunk 0 ----
    float4 aPre[4];
    #pragma unroll
    for (int i = 0; i < 4; i++)
        aPre[i] = *(const float4*)(keyb + (size_t)rowA[i] * E + cgA[i]);
    #pragma unroll
    for (int i = 0; i < 4; i++) {
        int li = tid + i * 256;
        int r = li >> 5, cg = li & 31;
        cp16(stB[0] + r * SB + cg * 4, g_wb + r * A + cg * 4);
    }
    asm volatile("cp.async.commit_group;");
    #pragma unroll
    for (int i = 0; i < 4; i++) {
        float4 t4 = make_float4(cvt_tf32(aPre[i].x), cvt_tf32(aPre[i].y),
                                cvt_tf32(aPre[i].z), cvt_tf32(aPre[i].w));
        *(float4*)(sA + rowA[i] * SA + cgA[i]) = t4;
    }
    asm volatile("cp.async.wait_group 0;");
    __syncthreads();

    for (int c = 0; c < NCHUNK; c++) {
        float* sB = stB[c & 1];
        bool has_next = (c + 1 < NCHUNK);
        // prefetch chunk c+1
        if (has_next) {
            if (c + 1 < 16) {
                int e0 = (c + 1) * KC;
                #pragma unroll
                for (int i = 0; i < 4; i++)
                    aPre[i] = *(const float4*)(keyb + (size_t)rowA[i] * E + e0 + cgA[i]);
            } else {
                #pragma unroll
                for (int i = 0; i < 4; i++)
                    aPre[i] = *(const float4*)(featb + (size_t)rowA[i] * F + cgA[i]);
            }
            const float* wsrc = g_wb + (size_t)(c + 1) * KC * A;
            float* sBn = stB[(c + 1) & 1];
            #pragma unroll
            for (int i = 0; i < 4; i++) {
                int li = tid + i * 256;
                int r = li >> 5, cg = li & 31;
                cp16(sBn + r * SB + cg * 4, wsrc + r * A + cg * 4);
            }
            asm volatile("cp.async.commit_group;");
        }

        // ---- 4 k-steps of m16n8k8 (pure LDS + HMMA) ----
        #pragma unroll
        for (int ks = 0; ks < 4; ks++) {
            int k0 = ks * 8;
            uint32_t af[4][4];
            #pragma unroll
            for (int mf = 0; mf < 4; mf++) {
                int rbase = warp_m * 64 + mf * 16 + (lane >> 2);
                int kcol = k0 + (lane & 3);
                af[mf][0] = __float_as_uint(sA[rbase * SA + kcol]);
                af[mf][1] = __float_as_uint(sA[(rbase + 8) * SA + kcol]);
                af[mf][2] = __float_as_uint(sA[rbase * SA + kcol + 4]);
                af[mf][3] = __float_as_uint(sA[(rbase + 8) * SA + kcol + 4]);
            }
            uint32_t bf[4][2];
            #pragma unroll
            for (int nf = 0; nf < 4; nf++) {
                int col = warp_n * 32 + nf * 8 + (lane >> 2);
                int krow = k0 + (lane & 3);
                bf[nf][0] = __float_as_uint(sB[krow * SB + col]);
                bf[nf][1] = __float_as_uint(sB[(krow + 4) * SB + col]);
            }
            #pragma unroll
            for (int mf = 0; mf < 4; mf++)
                #pragma unroll
                for (int nf = 0; nf < 4; nf++)
                    mma_tf32(acc[mf][nf][0], acc[mf][nf][1],
                             acc[mf][nf][2], acc[mf][nf][3],
                             af[mf][0], af[mf][1], af[mf][2], af[mf][3],
                             bf[nf][0], bf[nf][1]);
        }
        __syncthreads();                 // A readers done

        if (has_next) {
            #pragma unroll
            for (int i = 0; i < 4; i++) {
                float4 t4 = make_float4(cvt_tf32(aPre[i].x), cvt_tf32(aPre[i].y),
                                        cvt_tf32(aPre[i].z), cvt_tf32(aPre[i].w));
                *(float4*)(sA + rowA[i] * SA + cgA[i]) = t4;
            }
            asm volatile("cp.async.wait_group 0;");
            __syncthreads();
        }
    }

    // ---- epilogue: e[t] = sum_a v[a] * tanh(q[a] + S[t,a]) ----
    float part[4][2];
    #pragma unroll
    for (int mf = 0; mf < 4; mf++) { part[mf][0] = 0.f; part[mf][1] = 0.f; }

    #pragma unroll
    for (int nf = 0; nf < 4; nf++) {
        int c0 = warp_n * 32 + nf * 8 + 2 * (lane & 3);
        float qv0 = g_q[b * A + c0],     qv1 = g_q[b * A + c0 + 1];
        float vv0 = v[c0],               vv1 = v[c0 + 1];
        #pragma unroll
        for (int mf = 0; mf < 4; mf++) {
            part[mf][0] += vv0 * tanhf(qv0 + acc[mf][nf][0])
                         + vv1 * tanhf(qv1 + acc[mf][nf][1]);
            part[mf][1] += vv0 * tanhf(qv0 + acc[mf][nf][2])
                         + vv1 * tanhf(qv1 + acc[mf][nf][3]);
        }
    }

    __syncthreads();
    float* red = dsm;                // reuse: [128][5]
    #pragma unroll
    for (int mf = 0; mf < 4; mf++) {
        #pragma unroll
        for (int r = 0; r < 2; r++) {
            float p = part[mf][r];
            p += __shfl_xor_sync(0xFFFFFFFFu, p, 1);
            p += __shfl_xor_sync(0xFFFFFFFFu, p, 2);
            if ((lane & 3) == 0) {
                int row = warp_m * 64 + mf * 16 + (lane >> 2) + r * 8;
                red[row * 5 + warp_n] = p;
            }
        }
    }
    __syncthreads();

    if (tid < TM) {
        float s = red[tid * 5 + 0] + red[tid * 5 + 1]
                + red[tid * 5 + 2] + red[tid * 5 + 3];
        int t = t0 + tid;
        int mode = g_maskmode;
        g_e[b * T + t] = read_mask(mask, b * T + t, mode) ? -INFINITY : s;
    }
}

// ---------------------------------------------------------------------------
// 4) softmax over T per batch -> weights into d_out[B*E ..]
// ---------------------------------------------------------------------------
__global__ void softmax_kernel(float* __restrict__ out) {
    int b = blockIdx.x;
    int tid = threadIdx.x;          // 256 threads, 4 elems each
    __shared__ float sred[256];

    float vals[4];
    float m = -INFINITY;
    #pragma unroll
    for (int i = 0; i < 4; i++) {
        vals[i] = g_e[b * T + tid + i * 256];
        m = fmaxf(m, vals[i]);
    }
    sred[tid] = m; __syncthreads();
    for (int s = 128; s > 0; s >>= 1) {
        if (tid < s) sred[tid] = fmaxf(sred[tid], sred[tid + s]);
        __syncthreads();
    }
    m = sred[0]; __syncthreads();

    float sum = 0.f;
    #pragma unroll
    for (int i = 0; i < 4; i++) {
        vals[i] = expf(vals[i] - m);
        sum += vals[i];
    }
    sred[tid] = sum; __syncthreads();
    for (int s = 128; s > 0; s >>= 1) {
        if (tid < s) sred[tid] += sred[tid + s];
        __syncthreads();
    }
    float inv = 1.f / sred[0];

    float* w = out + B * E + (size_t)b * T;
    #pragma unroll
    for (int i = 0; i < 4; i++) w[tid + i * 256] = vals[i] * inv;
}

// ---------------------------------------------------------------------------
// 5) context: 16 T-chunks, 2-way t-split per block (256 thr), then reduce
// ---------------------------------------------------------------------------
__global__ void ctx_part_kernel(const float* __restrict__ key,
                                const float* __restrict__ out) {
    int b = blockIdx.y;
    int c = blockIdx.x;             // 0..15, 64 t each
    int tid = threadIdx.x;          // 256
    int e4 = tid & 127, h = tid >> 7;
    const float* w = out + B * E + (size_t)b * T + c * 64 + h * 32;
    const float4* kp = (const float4*)(key + (size_t)b * T * E)
                     + (size_t)(c * 64 + h * 32) * (E / 4) + e4;
    float4 acc = make_float4(0.f, 0.f, 0.f, 0.f);
    #pragma unroll 8
    for (int t = 0; t < 32; t++) {
        float4 k4 = kp[(size_t)t * (E / 4)];
        float wt = w[t];
        acc.x += wt * k4.x; acc.y += wt * k4.y;
        acc.z += wt * k4.z; acc.w += wt * k4.w;
    }
    __shared__ float4 sred[256];
    sred[tid] = acc;
    __syncthreads();
    if (h == 0) {
        float4 o = sred[tid];
        float4 p = sred[tid + 128];
        o.x += p.x; o.y += p.y; o.z += p.z; o.w += p.w;
        g_ctxpart4[(b * 16 + c) * (E / 4) + e4] = o;
    }
}

__global__ void ctx_reduce_kernel(float* __restrict__ out) {
    int b = blockIdx.x;
    int e4 = threadIdx.x;           // 128
    float4 s = make_float4(0.f, 0.f, 0.f, 0.f);
    #pragma unroll
    for (int c = 0; c < 16; c++) {
        float4 p = g_ctxpart4[(b * 16 + c) * (E / 4) + e4];
        s.x += p.x; s.y += p.y; s.z += p.z; s.w += p.w;
    }
    float* o = out + (size_t)b * E + e4 * 4;
    o[0] = s.x; o[1] = s.y; o[2] = s.z; o[3] = s.w;
}

// ---------------------------------------------------------------------------
extern "C" void kernel_launch(void* const* d_in, const int* in_sizes, int n_in,
                              void* d_out, int out_size) {
    const float* query  = (const float*)d_in[0];
    const float* key    = (const float*)d_in[1];
    const float* cat    = (const float*)d_in[2];
    const void*  mask   = (const void*)d_in[3];
    const float* Wq     = (const float*)d_in[4];
    const float* Wk     = (const float*)d_in[5];
    const float* conv_w = (const float*)d_in[6];
    const float* gamma  = (const float*)d_in[7];
    const float* beta   = (const float*)d_in[8];
    const float* mean   = (const float*)d_in[9];
    const float* var    = (const float*)d_in[10];
    const float* Wloc   = (const float*)d_in[11];
    const float* v      = (const float*)d_in[12];
    float* out = (float*)d_out;

    cudaFuncSetAttribute(energy_kernel,
                         cudaFuncAttributeMaxDynamicSharedMemorySize, SMEM_BYTES);

    mask_mode_kernel<<<1, 256>>>((const unsigned int*)mask);
    wb_kernel<<<((E + F) * A + 1023) / 1024, 1024>>>(Wk, Wloc);
    qproj_kernel<<<B, 1024>>>(query, Wq);
    loc_kernel<<<dim3(T / 128, B), 128>>>(cat, conv_w, gamma, beta, mean, var);
    energy_kernel<<<dim3(T / TM, B), 256, SMEM_BYTES>>>(key, mask, v);
    softmax_kernel<<<B, 256>>>(out);
    ctx_part_kernel<<<dim3(16, B), 256>>>(key, out);
    ctx_reduce_kernel<<<B, 128>>>(out);
}

// round 7
// speedup vs baseline: 1.1156x; 1.0724x over previous
#include <cuda_runtime.h>
#include <math.h>
#include <stdint.h>

#define B 64
#define T 1024
#define E 512
#define R 1024
#define A 128
#define F 32
#define KS 31
#define PADC 15

#define TM 128          // t-tile of energy GEMM
#define KC 32           // k-chunk
#define NCHUNK 17       // 16 key chunks + 1 feat/Wloc chunk
#define SA 36           // sA stride (conflict-free A frags)
#define SB 136          // sB stride (conflict-free B frags)
#define SZA (TM * SA)   // 4608 floats
#define SZB (KC * SB)   // 4352 floats
#define SMEM_BYTES ((SZA + 2 * SZB) * 4)   // 53248 B

// prep grid layout
#define NB_LOC  256     // 4 per batch x 64 (256 t each)
#define NB_QP   64
#define NB_WB   68      // 68 * 1024 = 69632 = (E+F)*A
#define NB_PREP (NB_LOC + NB_QP + NB_WB + 1)

// scratch (allocation-free rule: __device__ globals)
__device__ float  g_q[B * A];                         // 32 KB
__device__ float4 g_feat4[(size_t)B * T * F / 4];     // 8 MB, [B][T][F]
__device__ float  g_e[B * T];                         // 256 KB
__device__ float4 g_ctxpart4[B * 16 * E / 4];         // 2 MB
__device__ float  g_wb[(E + F) * A];                  // 278 KB tf32-rounded Wk;Wloc
__device__ int    g_maskmode;                         // 0=u8, 1=i32, 2=f32

// ---------------------------------------------------------------------------
// helpers
// ---------------------------------------------------------------------------
__device__ __forceinline__ void cp16(float* dst_smem, const float* src) {
    uint32_t d = (uint32_t)__cvta_generic_to_shared(dst_smem);
    asm volatile("cp.async.ca.shared.global [%0], [%1], 16;" :: "r"(d), "l"(src));
}
__device__ __forceinline__ float cvt_tf32(float x) {
    uint32_t u;
    asm("cvt.rna.tf32.f32 %0, %1;" : "=r"(u) : "f"(x));
    return __uint_as_float(u);
}
__device__ __forceinline__ void mma_tf32(float& c0, float& c1, float& c2, float& c3,
                                         uint32_t a0, uint32_t a1, uint32_t a2, uint32_t a3,
                                         uint32_t b0, uint32_t b1) {
    asm volatile(
        "mma.sync.aligned.m16n8k8.row.col.f32.tf32.tf32.f32 "
        "{%0,%1,%2,%3}, {%4,%5,%6,%7}, {%8,%9}, {%0,%1,%2,%3};"
        : "+f"(c0), "+f"(c1), "+f"(c2), "+f"(c3)
        : "r"(a0), "r"(a1), "r"(a2), "r"(a3), "r"(b0), "r"(b1));
}
__device__ __forceinline__ bool read_mask(const void* m, int idx, int mode) {
    if (mode == 1) return ((const int*)m)[idx] != 0;
    if (mode == 2) return ((const float*)m)[idx] != 0.f;
    return ((const unsigned char*)m)[idx] != 0;
}

// ---------------------------------------------------------------------------
// PREP: fused loc-conv / qproj / wb / mask-sniff  (independent block ranges)
// ---------------------------------------------------------------------------
__global__ void __launch_bounds__(256)
prep_kernel(const float* __restrict__ query,
            const float* __restrict__ Wq,
            const float* __restrict__ cat,
            const float* __restrict__ conv_w,
            const float* __restrict__ gamma,
            const float* __restrict__ beta,
            const float* __restrict__ mean,
            const float* __restrict__ var,
            const float* __restrict__ Wk,
            const float* __restrict__ Wloc,
            const unsigned int* __restrict__ maskw) {
    int blk = blockIdx.x;
    int tid = threadIdx.x;          // 256

    if (blk < NB_LOC) {
        // ---------------- loc: conv1d -> relu -> BN -> g_feat ----------------
        int b  = blk >> 2;
        int t0 = (blk & 3) * 256;

        __shared__ float xs[2][288];            // 256 + 30 halo (+2 pad)
        __shared__ float cwT[2 * KS * F];       // [ch][k][f] (f contiguous)
        __shared__ float bnS[F], bnB[F];

        for (int idx = tid; idx < 2 * 286; idx += 256) {
            int ch = idx / 286, p = idx % 286;
            int tt = t0 - PADC + p;
            xs[ch][p] = (tt >= 0 && tt < T)
                      ? cat[(size_t)b * 2 * T + (size_t)ch * T + tt] : 0.f;
        }
        for (int idx = tid; idx < 2 * KS * F; idx += 256) {
            int f = idx & 31;
            int rest = idx >> 5;                 // ch*31 + k
            int ch = rest / KS, k = rest % KS;
            cwT[idx] = conv_w[(f * 2 + ch) * KS + k];
        }
        if (tid < F) {
            float s = rsqrtf(var[tid] + 1e-5f) * gamma[tid];
            bnS[tid] = s;
            bnB[tid] = beta[tid] - mean[tid] * s;
        }
        __syncthreads();

        float4 acc[8];
        #pragma unroll
        for (int u = 0; u < 8; u++) acc[u] = make_float4(0.f, 0.f, 0.f, 0.f);

        #pragma unroll 1
        for (int ch = 0; ch < 2; ch++) {
            #pragma unroll 1
            for (int k = 0; k < KS; k++) {
                float xv = xs[ch][tid + k];
                const float4* c4 = (const float4*)(cwT + (ch * KS + k) * F);
                #pragma unroll
                for (int u = 0; u < 8; u++) {
                    float4 c = c4[u];
                    acc[u].x += xv * c.x; acc[u].y += xv * c.y;
                    acc[u].z += xv * c.z; acc[u].w += xv * c.w;
                }
            }
        }

        size_t base = ((size_t)b * T + t0 + tid) * (F / 4);
        #pragma unroll
        for (int u = 0; u < 8; u++) {
            int f0 = u * 4;
            float4 o;
            o.x = cvt_tf32(fmaxf(acc[u].x, 0.f) * bnS[f0 + 0] + bnB[f0 + 0]);
            o.y = cvt_tf32(fmaxf(acc[u].y, 0.f) * bnS[f0 + 1] + bnB[f0 + 1]);
            o.z = cvt_tf32(fmaxf(acc[u].z, 0.f) * bnS[f0 + 2] + bnB[f0 + 2]);
            o.w = cvt_tf32(fmaxf(acc[u].w, 0.f) * bnS[f0 + 3] + bnB[f0 + 3]);
            g_feat4[base + u] = o;
        }
    } else if (blk < NB_LOC + NB_QP) {
        // ---------------- qproj: q = query @ Wq ----------------
        int b = blk - NB_LOC;
        int g = tid >> 7, a = tid & 127;        // 2 groups x 512 r
        __shared__ float sred[2][128];
        const float* qb = query + (size_t)b * R + g * 512;
        const float* wp = Wq + (size_t)(g * 512) * A + a;
        float acc = 0.f;
        #pragma unroll 8
        for (int r = 0; r < 512; r++)
            acc += qb[r] * wp[(size_t)r * A];
        sred[g][a] = acc;
        __syncthreads();
        if (g == 0)
            g_q[b * A + a] = sred[0][a] + sred[1][a];
    } else if (blk < NB_LOC + NB_QP + NB_WB) {
        // ---------------- wb: tf32-round Wk ++ Wloc ----------------
        int base = (blk - NB_LOC - NB_QP) * 1024;
        #pragma unroll
        for (int i = 0; i < 4; i++) {
            int idx = base + i * 256 + tid;
            float x = (idx < E * A) ? Wk[idx] : Wloc[idx - E * A];
            g_wb[idx] = cvt_tf32(x);
        }
    } else {
        // ---------------- mask dtype sniff ----------------
        __shared__ int s_not_int, s_not_flt;
        if (tid == 0) { s_not_int = 0; s_not_flt = 0; }
        __syncthreads();
        int not_int = 0, not_flt = 0;
        for (int i = tid; i < (B * T) / 4; i += 256) {
            unsigned int x = maskw[i];
            if (x > 1u) not_int = 1;
            if (x != 0u && x != 0x3F800000u) not_flt = 1;
        }
        if (not_int) atomicOr(&s_not_int, 1);
        if (not_flt) atomicOr(&s_not_flt, 1);
        __syncthreads();
        if (tid == 0)
            g_maskmode = (!s_not_int) ? 1 : ((!s_not_flt) ? 2 : 0);
    }
}

// ---------------------------------------------------------------------------
// energy: tf32 MMA GEMM 128x128x(512+32)
//   A: register-prefetch double buffer (cvt at STS), B: cp.async 2-stage
// ---------------------------------------------------------------------------
__global__ void __launch_bounds__(256, 2)
energy_kernel(const float* __restrict__ key,
              const void* __restrict__ mask,
              const float* __restrict__ v) {
    int b  = blockIdx.y;
    int t0 = blockIdx.x * TM;
    int tid = threadIdx.x;
    int lane = tid & 31;
    int wid  = tid >> 5;
    int warp_m = wid >> 2;          // 0..1 (64 rows each)
    int warp_n = wid & 3;           // 0..3 (32 cols each)

    extern __shared__ float dsm[];
    float* sA = dsm;                          // [128][36]
    float* stB[2] = {dsm + SZA, dsm + SZA + SZB};

    float acc[4][4][4];
    #pragma unroll
    for (int i = 0; i < 4; i++)
        #pragma unroll
        for (int j = 0; j < 4; j++)
            #pragma unroll
            for (int r = 0; r < 4; r++) acc[i][j][r] = 0.f;

    const float* keyb  = key + (size_t)b * T * E + (size_t)t0 * E;
    const float* featb = (const float*)g_feat4 + ((size_t)b * T + t0) * F;

    int rowA[4], cgA[4];
    #pragma unroll
    for (int i = 0; i < 4; i++) {
        int li = tid + i * 256;
        rowA[i] = li >> 3;
        cgA[i]  = (li & 7) * 4;
    }

    // ---- prologue: chunk 0 ----
    float4 aPre[4];
    #pragma unroll
    for (int i = 0; i < 4; i++)
        aPre[i] = *(const float4*)(keyb + (size_t)rowA[i] * E + cgA[i]);
    #pragma unroll
    for (int i = 0; i < 4; i++) {
        int li = tid + i * 256;
        int r = li >> 5, cg = li & 31;
        cp16(stB[0] + r * SB + cg * 4, g_wb + r * A + cg * 4);
    }
    asm volatile("cp.async.commit_group;");
    #pragma unroll
    for (int i = 0; i < 4; i++) {
        float4 t4 = make_float4(cvt_tf32(aPre[i].x), cvt_tf32(aPre[i].y),
                                cvt_tf32(aPre[i].z), cvt_tf32(aPre[i].w));
        *(float4*)(sA + rowA[i] * SA + cgA[i]) = t4;
    }
    asm volatile("cp.async.wait_group 0;");
    __syncthreads();

    for (int c = 0; c < NCHUNK; c++) {
        float* sB = stB[c & 1];
        bool has_next = (c + 1 < NCHUNK);
        if (has_next) {
            if (c + 1 < 16) {
                int e0 = (c + 1) * KC;
                #pragma unroll
                for (int i = 0; i < 4; i++)
                    aPre[i] = *(const float4*)(keyb + (size_t)rowA[i] * E + e0 + cgA[i]);
            } else {
                #pragma unroll
                for (int i = 0; i < 4; i++)
                    aPre[i] = *(const float4*)(featb + (size_t)rowA[i] * F + cgA[i]);
            }
            const float* wsrc = g_wb + (size_t)(c + 1) * KC * A;
            float* sBn = stB[(c + 1) & 1];
            #pragma unroll
            for (int i = 0; i < 4; i++) {
                int li = tid + i * 256;
                int r = li >> 5, cg = li & 31;
                cp16(sBn + r * SB + cg * 4, wsrc + r * A + cg * 4);
            }
            asm volatile("cp.async.commit_group;");
        }

        #pragma unroll
        for (int ks = 0; ks < 4; ks++) {
            int k0 = ks * 8;
            uint32_t af[4][4];
            #pragma unroll
            for (int mf = 0; mf < 4; mf++) {
                int rbase = warp_m * 64 + mf * 16 + (lane >> 2);
                int kcol = k0 + (lane & 3);
                af[mf][0] = __float_as_uint(sA[rbase * SA + kcol]);
                af[mf][1] = __float_as_uint(sA[(rbase + 8) * SA + kcol]);
                af[mf][2] = __float_as_uint(sA[rbase * SA + kcol + 4]);
                af[mf][3] = __float_as_uint(sA[(rbase + 8) * SA + kcol + 4]);
            }
            uint32_t bf[4][2];
            #pragma unroll
            for (int nf = 0; nf < 4; nf++) {
                int col = warp_n * 32 + nf * 8 + (lane >> 2);
                int krow = k0 + (lane & 3);
                bf[nf][0] = __float_as_uint(sB[krow * SB + col]);
                bf[nf][1] = __float_as_uint(sB[(krow + 4) * SB + col]);
            }
            #pragma unroll
            for (int mf = 0; mf < 4; mf++)
                #pragma unroll
                for (int nf = 0; nf < 4; nf++)
                    mma_tf32(acc[mf][nf][0], acc[mf][nf][1],
                             acc[mf][nf][2], acc[mf][nf][3],
                             af[mf][0], af[mf][1], af[mf][2], af[mf][3],
                             bf[nf][0], bf[nf][1]);
        }
        __syncthreads();

        if (has_next) {
            #pragma unroll
            for (int i = 0; i < 4; i++) {
                float4 t4 = make_float4(cvt_tf32(aPre[i].x), cvt_tf32(aPre[i].y),
                                        cvt_tf32(aPre[i].z), cvt_tf32(aPre[i].w));
                *(float4*)(sA + rowA[i] * SA + cgA[i]) = t4;
            }
            asm volatile("cp.async.wait_group 0;");
            __syncthreads();
        }
    }

    // ---- epilogue: e[t] = sum_a v[a] * tanh(q[a] + S[t,a]) ----
    float part[4][2];
    #pragma unroll
    for (int mf = 0; mf < 4; mf++) { part[mf][0] = 0.f; part[mf][1] = 0.f; }

    #pragma unroll
    for (int nf = 0; nf < 4; nf++) {
        int c0 = warp_n * 32 + nf * 8 + 2 * (lane & 3);
        float qv0 = g_q[b * A + c0],     qv1 = g_q[b * A + c0 + 1];
        float vv0 = v[c0],               vv1 = v[c0 + 1];
        #pragma unroll
        for (int mf = 0; mf < 4; mf++) {
            part[mf][0] += vv0 * tanhf(qv0 + acc[mf][nf][0])
                         + vv1 * tanhf(qv1 + acc[mf][nf][1]);
            part[mf][1] += vv0 * tanhf(qv0 + acc[mf][nf][2])
                         + vv1 * tanhf(qv1 + acc[mf][nf][3]);
        }
    }

    __syncthreads();
    float* red = dsm;                // reuse: [128][5]
    #pragma unroll
    for (int mf = 0; mf < 4; mf++) {
        #pragma unroll
        for (int r = 0; r < 2; r++) {
            float p = part[mf][r];
            p += __shfl_xor_sync(0xFFFFFFFFu, p, 1);
            p += __shfl_xor_sync(0xFFFFFFFFu, p, 2);
            if ((lane & 3) == 0) {
                int row = warp_m * 64 + mf * 16 + (lane >> 2) + r * 8;
                red[row * 5 + warp_n] = p;
            }
        }
    }
    __syncthreads();

    if (tid < TM) {
        float s = red[tid * 5 + 0] + red[tid * 5 + 1]
                + red[tid * 5 + 2] + red[tid * 5 + 3];
        int t = t0 + tid;
        int mode = g_maskmode;
        g_e[b * T + t] = read_mask(mask, b * T + t, mode) ? -INFINITY : s;
    }
}

// ---------------------------------------------------------------------------
// softmax over T per batch -> weights into d_out[B*E ..]
// ---------------------------------------------------------------------------
__global__ void softmax_kernel(float* __restrict__ out) {
    int b = blockIdx.x;
    int tid = threadIdx.x;          // 256 threads, 4 elems each
    __shared__ float sred[256];

    float vals[4];
    float m = -INFINITY;
    #pragma unroll
    for (int i = 0; i < 4; i++) {
        vals[i] = g_e[b * T + tid + i * 256];
        m = fmaxf(m, vals[i]);
    }
    sred[tid] = m; __syncthreads();
    for (int s = 128; s > 0; s >>= 1) {
        if (tid < s) sred[tid] = fmaxf(sred[tid], sred[tid + s]);
        __syncthreads();
    }
    m = sred[0]; __syncthreads();

    float sum = 0.f;
    #pragma unroll
    for (int i = 0; i < 4; i++) {
        vals[i] = expf(vals[i] - m);
        sum += vals[i];
    }
    sred[tid] = sum; __syncthreads();
    for (int s = 128; s > 0; s >>= 1) {
        if (tid < s) sred[tid] += sred[tid + s];
        __syncthreads();
    }
    float inv = 1.f / sred[0];

    float* w = out + B * E + (size_t)b * T;
    #pragma unroll
    for (int i = 0; i < 4; i++) w[tid + i * 256] = vals[i] * inv;
}

// ---------------------------------------------------------------------------
// context: 16 T-chunks, 2-way t-split per block (256 thr), then reduce
// ---------------------------------------------------------------------------
__global__ void ctx_part_kernel(const float* __restrict__ key,
                                const float* __restrict__ out) {
    int b = blockIdx.y;
    int c = blockIdx.x;             // 0..15, 64 t each
    int tid = threadIdx.x;          // 256
    int e4 = tid & 127, h = tid >> 7;
    const float* w = out + B * E + (size_t)b * T + c * 64 + h * 32;
    const float4* kp = (const float4*)(key + (size_t)b * T * E)
                     + (size_t)(c * 64 + h * 32) * (E / 4) + e4;
    float4 acc = make_float4(0.f, 0.f, 0.f, 0.f);
    #pragma unroll 8
    for (int t = 0; t < 32; t++) {
        float4 k4 = kp[(size_t)t * (E / 4)];
        float wt = w[t];
        acc.x += wt * k4.x; acc.y += wt * k4.y;
        acc.z += wt * k4.z; acc.w += wt * k4.w;
    }
    __shared__ float4 sred[256];
    sred[tid] = acc;
    __syncthreads();
    if (h == 0) {
        float4 o = sred[tid];
        float4 p = sred[tid + 128];
        o.x += p.x; o.y += p.y; o.z += p.z; o.w += p.w;
        g_ctxpart4[(b * 16 + c) * (E / 4) + e4] = o;
    }
}

__global__ void ctx_reduce_kernel(float* __restrict__ out) {
    int b = blockIdx.x;
    int e4 = threadIdx.x;           // 128
    float4 s = make_float4(0.f, 0.f, 0.f, 0.f);
    #pragma unroll
    for (int c = 0; c < 16; c++) {
        float4 p = g_ctxpart4[(b * 16 + c) * (E / 4) + e4];
        s.x += p.x; s.y += p.y; s.z += p.z; s.w += p.w;
    }
    float* o = out + (size_t)b * E + e4 * 4;
    o[0] = s.x; o[1] = s.y; o[2] = s.z; o[3] = s.w;
}

// ---------------------------------------------------------------------------
extern "C" void kernel_launch(void* const* d_in, const int* in_sizes, int n_in,
                              void* d_out, int out_size) {
    const float* query  = (const float*)d_in[0];
    const float* key    = (const float*)d_in[1];
    const float* cat    = (const float*)d_in[2];
    const void*  mask   = (const void*)d_in[3];
    const float* Wq     = (const float*)d_in[4];
    const float* Wk     = (const float*)d_in[5];
    const float* conv_w = (const float*)d_in[6];
    const float* gamma  = (const float*)d_in[7];
    const float* beta   = (const float*)d_in[8];
    const float* mean   = (const float*)d_in[9];
    const float* var    = (const float*)d_in[10];
    const float* Wloc   = (const float*)d_in[11];
    const float* v      = (const float*)d_in[12];
    float* out = (float*)d_out;

    cudaFuncSetAttribute(energy_kernel,
                         cudaFuncAttributeMaxDynamicSharedMemorySize, SMEM_BYTES);

    prep_kernel<<<NB_PREP, 256>>>(query, Wq, cat, conv_w, gamma, beta, mean, var,
                                  Wk, Wloc, (const unsigned int*)mask);
    energy_kernel<<<dim3(T / TM, B), 256, SMEM_BYTES>>>(key, mask, v);
    softmax_kernel<<<B, 256>>>(out);
    ctx_part_kernel<<<dim3(16, B), 256>>>(key, out);
    ctx_reduce_kernel<<<B, 128>>>(out);
}

// round 8
// speedup vs baseline: 1.1457x; 1.0270x over previous
#include <cuda_runtime.h>
#include <math.h>
#include <stdint.h>

#define B 64
#define T 1024
#define E 512
#define R 1024
#define A 128
#define F 32
#define KS 31
#define PADC 15

#define TM 128          // t-tile of energy GEMM
#define KC 32           // k-chunk
#define NCHUNK 17       // 16 key chunks + 1 feat/Wloc chunk
#define SA 36           // sA stride (conflict-free A frags)
#define SB 136          // sB stride (conflict-free B frags)
#define SZA (TM * SA)   // 4608 floats
#define SZB (KC * SB)   // 4352 floats
#define SMEM_BYTES ((SZA + 2 * SZB) * 4)   // 53248 B

// prep grid layout
#define NB_LOC  256     // 4 per batch x 64 (256 t each)
#define NB_QP   64
#define NB_WB   68      // 68 * 1024 = 69632 = (E+F)*A
#define NB_PREP (NB_LOC + NB_QP + NB_WB + 1)

// scratch (allocation-free rule: __device__ globals)
__device__ float  g_q[B * A];                         // 32 KB
__device__ float4 g_feat4[(size_t)B * T * F / 4];     // 8 MB, [B][T][F]
__device__ float  g_e[B * T];                         // 256 KB
__device__ float4 g_ctxpart4[B * 16 * E / 4];         // 2 MB
__device__ float  g_wb[(E + F) * A];                  // 278 KB tf32-rounded Wk;Wloc
__device__ int    g_maskmode;                         // 0=u8, 1=i32, 2=f32

// ---------------------------------------------------------------------------
// helpers
// ---------------------------------------------------------------------------
__device__ __forceinline__ void cp16(float* dst_smem, const float* src) {
    uint32_t d = (uint32_t)__cvta_generic_to_shared(dst_smem);
    asm volatile("cp.async.ca.shared.global [%0], [%1], 16;" :: "r"(d), "l"(src));
}
__device__ __forceinline__ float cvt_tf32(float x) {
    uint32_t u;
    asm("cvt.rna.tf32.f32 %0, %1;" : "=r"(u) : "f"(x));
    return __uint_as_float(u);
}
__device__ __forceinline__ void mma_tf32(float& c0, float& c1, float& c2, float& c3,
                                         uint32_t a0, uint32_t a1, uint32_t a2, uint32_t a3,
                                         uint32_t b0, uint32_t b1) {
    asm volatile(
        "mma.sync.aligned.m16n8k8.row.col.f32.tf32.tf32.f32 "
        "{%0,%1,%2,%3}, {%4,%5,%6,%7}, {%8,%9}, {%0,%1,%2,%3};"
        : "+f"(c0), "+f"(c1), "+f"(c2), "+f"(c3)
        : "r"(a0), "r"(a1), "r"(a2), "r"(a3), "r"(b0), "r"(b1));
}
__device__ __forceinline__ bool read_mask(const void* m, int idx, int mode) {
    if (mode == 1) return ((const int*)m)[idx] != 0;
    if (mode == 2) return ((const float*)m)[idx] != 0.f;
    return ((const unsigned char*)m)[idx] != 0;
}

// ---------------------------------------------------------------------------
// PREP: fused loc-conv / qproj / wb / mask-sniff  (independent block ranges)
// ---------------------------------------------------------------------------
__global__ void __launch_bounds__(256)
prep_kernel(const float* __restrict__ query,
            const float* __restrict__ Wq,
            const float* __restrict__ cat,
            const float* __restrict__ conv_w,
            const float* __restrict__ gamma,
            const float* __restrict__ beta,
            const float* __restrict__ mean,
            const float* __restrict__ var,
            const float* __restrict__ Wk,
            const float* __restrict__ Wloc,
            const unsigned int* __restrict__ maskw) {
    int blk = blockIdx.x;
    int tid = threadIdx.x;          // 256

    if (blk < NB_LOC) {
        // ---------------- loc: conv1d -> relu -> BN -> g_feat ----------------
        int b  = blk >> 2;
        int t0 = (blk & 3) * 256;

        __shared__ float xs[2][288];            // 256 + 30 halo (+2 pad)
        __shared__ float cwT[2 * KS * F];       // [ch][k][f] (f contiguous)
        __shared__ float bnS[F], bnB[F];

        for (int idx = tid; idx < 2 * 286; idx += 256) {
            int ch = idx / 286, p = idx % 286;
            int tt = t0 - PADC + p;
            xs[ch][p] = (tt >= 0 && tt < T)
                      ? cat[(size_t)b * 2 * T + (size_t)ch * T + tt] : 0.f;
        }
        for (int idx = tid; idx < 2 * KS * F; idx += 256) {
            int f = idx & 31;
            int rest = idx >> 5;                 // ch*31 + k
            int ch = rest / KS, k = rest % KS;
            cwT[idx] = conv_w[(f * 2 + ch) * KS + k];
        }
        if (tid < F) {
            float s = rsqrtf(var[tid] + 1e-5f) * gamma[tid];
            bnS[tid] = s;
            bnB[tid] = beta[tid] - mean[tid] * s;
        }
        __syncthreads();

        float4 acc[8];
        #pragma unroll
        for (int u = 0; u < 8; u++) acc[u] = make_float4(0.f, 0.f, 0.f, 0.f);

        #pragma unroll 1
        for (int ch = 0; ch < 2; ch++) {
            #pragma unroll 1
            for (int k = 0; k < KS; k++) {
                float xv = xs[ch][tid + k];
                const float4* c4 = (const float4*)(cwT + (ch * KS + k) * F);
                #pragma unroll
                for (int u = 0; u < 8; u++) {
                    float4 c = c4[u];
                    acc[u].x += xv * c.x; acc[u].y += xv * c.y;
                    acc[u].z += xv * c.z; acc[u].w += xv * c.w;
                }
            }
        }

        size_t base = ((size_t)b * T + t0 + tid) * (F / 4);
        #pragma unroll
        for (int u = 0; u < 8; u++) {
            int f0 = u * 4;
            float4 o;
            o.x = cvt_tf32(fmaxf(acc[u].x, 0.f) * bnS[f0 + 0] + bnB[f0 + 0]);
            o.y = cvt_tf32(fmaxf(acc[u].y, 0.f) * bnS[f0 + 1] + bnB[f0 + 1]);
            o.z = cvt_tf32(fmaxf(acc[u].z, 0.f) * bnS[f0 + 2] + bnB[f0 + 2]);
            o.w = cvt_tf32(fmaxf(acc[u].w, 0.f) * bnS[f0 + 3] + bnB[f0 + 3]);
            g_feat4[base + u] = o;
        }
    } else if (blk < NB_LOC + NB_QP) {
        // ---------------- qproj: q = query @ Wq ----------------
        int b = blk - NB_LOC;
        int g = tid >> 7, a = tid & 127;        // 2 groups x 512 r
        __shared__ float sred[2][128];
        const float* qb = query + (size_t)b * R + g * 512;
        const float* wp = Wq + (size_t)(g * 512) * A + a;
        float acc = 0.f;
        #pragma unroll 8
        for (int r = 0; r < 512; r++)
            acc += qb[r] * wp[(size_t)r * A];
        sred[g][a] = acc;
        __syncthreads();
        if (g == 0)
            g_q[b * A + a] = sred[0][a] + sred[1][a];
    } else if (blk < NB_LOC + NB_QP + NB_WB) {
        // ---------------- wb: tf32-round Wk ++ Wloc ----------------
        int base = (blk - NB_LOC - NB_QP) * 1024;
        #pragma unroll
        for (int i = 0; i < 4; i++) {
            int idx = base + i * 256 + tid;
            float x = (idx < E * A) ? Wk[idx] : Wloc[idx - E * A];
            g_wb[idx] = cvt_tf32(x);
        }
    } else {
        // ---------------- mask dtype sniff ----------------
        __shared__ int s_not_int, s_not_flt;
        if (tid == 0) { s_not_int = 0; s_not_flt = 0; }
        __syncthreads();
        int not_int = 0, not_flt = 0;
        for (int i = tid; i < (B * T) / 4; i += 256) {
            unsigned int x = maskw[i];
            if (x > 1u) not_int = 1;
            if (x != 0u && x != 0x3F800000u) not_flt = 1;
        }
        if (not_int) atomicOr(&s_not_int, 1);
        if (not_flt) atomicOr(&s_not_flt, 1);
        __syncthreads();
        if (tid == 0)
            g_maskmode = (!s_not_int) ? 1 : ((!s_not_flt) ? 2 : 0);
    }
}

// ---------------------------------------------------------------------------
// energy: tf32 MMA GEMM 128x128x(512+32)
//   A: register-prefetch double buffer (cvt at STS), B: cp.async 2-stage
// ---------------------------------------------------------------------------
__global__ void __launch_bounds__(256, 2)
energy_kernel(const float* __restrict__ key,
              const void* __restrict__ mask,
              const float* __restrict__ v) {
    int b  = blockIdx.y;
    int t0 = blockIdx.x * TM;
    int tid = threadIdx.x;
    int lane = tid & 31;
    int wid  = tid >> 5;
    int warp_m = wid >> 2;          // 0..1 (64 rows each)
    int warp_n = wid & 3;           // 0..3 (32 cols each)

    extern __shared__ float dsm[];
    float* sA = dsm;                          // [128][36]
    float* stB[2] = {dsm + SZA, dsm + SZA + SZB};

    float acc[4][4][4];
    #pragma unroll
    for (int i = 0; i < 4; i++)
        #pragma unroll
        for (int j = 0; j < 4; j++)
            #pragma unroll
            for (int r = 0; r < 4; r++) acc[i][j][r] = 0.f;

    const float* keyb  = key + (size_t)b * T * E + (size_t)t0 * E;
    const float* featb = (const float*)g_feat4 + ((size_t)b * T + t0) * F;

    int rowA[4], cgA[4];
    #pragma unroll
    for (int i = 0; i < 4; i++) {
        int li = tid + i * 256;
        rowA[i] = li >> 3;
        cgA[i]  = (li & 7) * 4;
    }

    // ---- prologue: chunk 0 ----
    float4 aPre[4];
    #pragma unroll
    for (int i = 0; i < 4; i++)
        aPre[i] = *(const float4*)(keyb + (size_t)rowA[i] * E + cgA[i]);
    #pragma unroll
    for (int i = 0; i < 4; i++) {
        int li = tid + i * 256;
        int r = li >> 5, cg = li & 31;
        cp16(stB[0] + r * SB + cg * 4, g_wb + r * A + cg * 4);
    }
    asm volatile("cp.async.commit_group;");
    #pragma unroll
    for (int i = 0; i < 4; i++) {
        float4 t4 = make_float4(cvt_tf32(aPre[i].x), cvt_tf32(aPre[i].y),
                                cvt_tf32(aPre[i].z), cvt_tf32(aPre[i].w));
        *(float4*)(sA + rowA[i] * SA + cgA[i]) = t4;
    }
    asm volatile("cp.async.wait_group 0;");
    __syncthreads();

    for (int c = 0; c < NCHUNK; c++) {
        float* sB = stB[c & 1];
        bool has_next = (c + 1 < NCHUNK);
        if (has_next) {
            if (c + 1 < 16) {
                int e0 = (c + 1) * KC;
                #pragma unroll
                for (int i = 0; i < 4; i++)
                    aPre[i] = *(const float4*)(keyb + (size_t)rowA[i] * E + e0 + cgA[i]);
            } else {
                #pragma unroll
                for (int i = 0; i < 4; i++)
                    aPre[i] = *(const float4*)(featb + (size_t)rowA[i] * F + cgA[i]);
            }
            const float* wsrc = g_wb + (size_t)(c + 1) * KC * A;
            float* sBn = stB[(c + 1) & 1];
            #pragma unroll
            for (int i = 0; i < 4; i++) {
                int li = tid + i * 256;
                int r = li >> 5, cg = li & 31;
                cp16(sBn + r * SB + cg * 4, wsrc + r * A + cg * 4);
            }
            asm volatile("cp.async.commit_group;");
        }

        #pragma unroll
        for (int ks = 0; ks < 4; ks++) {
            int k0 = ks * 8;
            uint32_t af[4][4];
            #pragma unroll
            for (int mf = 0; mf < 4; mf++) {
                int rbase = warp_m * 64 + mf * 16 + (lane >> 2);
                int kcol = k0 + (lane & 3);
                af[mf][0] = __float_as_uint(sA[rbase * SA + kcol]);
                af[mf][1] = __float_as_uint(sA[(rbase + 8) * SA + kcol]);
                af[mf][2] = __float_as_uint(sA[rbase * SA + kcol + 4]);
                af[mf][3] = __float_as_uint(sA[(rbase + 8) * SA + kcol + 4]);
            }
            uint32_t bf[4][2];
            #pragma unroll
            for (int nf = 0; nf < 4; nf++) {
                int col = warp_n * 32 + nf * 8 + (lane >> 2);
                int krow = k0 + (lane & 3);
                bf[nf][0] = __float_as_uint(sB[krow * SB + col]);
                bf[nf][1] = __float_as_uint(sB[(krow + 4) * SB + col]);
            }
            #pragma unroll
            for (int mf = 0; mf < 4; mf++)
                #pragma unroll
                for (int nf = 0; nf < 4; nf++)
                    mma_tf32(acc[mf][nf][0], acc[mf][nf][1],
                             acc[mf][nf][2], acc[mf][nf][3],
                             af[mf][0], af[mf][1], af[mf][2], af[mf][3],
                             bf[nf][0], bf[nf][1]);
        }
        __syncthreads();

        if (has_next) {
            #pragma unroll
            for (int i = 0; i < 4; i++) {
                float4 t4 = make_float4(cvt_tf32(aPre[i].x), cvt_tf32(aPre[i].y),
                                        cvt_tf32(aPre[i].z), cvt_tf32(aPre[i].w));
                *(float4*)(sA + rowA[i] * SA + cgA[i]) = t4;
            }
            asm volatile("cp.async.wait_group 0;");
            __syncthreads();
        }
    }

    // ---- epilogue: e[t] = sum_a v[a] * tanh(q[a] + S[t,a]) ----
    float part[4][2];
    #pragma unroll
    for (int mf = 0; mf < 4; mf++) { part[mf][0] = 0.f; part[mf][1] = 0.f; }

    #pragma unroll
    for (int nf = 0; nf < 4; nf++) {
        int c0 = warp_n * 32 + nf * 8 + 2 * (lane & 3);
        float qv0 = g_q[b * A + c0],     qv1 = g_q[b * A + c0 + 1];
        float vv0 = v[c0],               vv1 = v[c0 + 1];
        #pragma unroll
        for (int mf = 0; mf < 4; mf++) {
            part[mf][0] += vv0 * tanhf(qv0 + acc[mf][nf][0])
                         + vv1 * tanhf(qv1 + acc[mf][nf][1]);
            part[mf][1] += vv0 * tanhf(qv0 + acc[mf][nf][2])
                         + vv1 * tanhf(qv1 + acc[mf][nf][3]);
        }
    }

    __syncthreads();
    float* red = dsm;                // reuse: [128][5]
    #pragma unroll
    for (int mf = 0; mf < 4; mf++) {
        #pragma unroll
        for (int r = 0; r < 2; r++) {
            float p = part[mf][r];
            p += __shfl_xor_sync(0xFFFFFFFFu, p, 1);
            p += __shfl_xor_sync(0xFFFFFFFFu, p, 2);
            if ((lane & 3) == 0) {
                int row = warp_m * 64 + mf * 16 + (lane >> 2) + r * 8;
                red[row * 5 + warp_n] = p;
            }
        }
    }
    __syncthreads();

    if (tid < TM) {
        float s = red[tid * 5 + 0] + red[tid * 5 + 1]
                + red[tid * 5 + 2] + red[tid * 5 + 3];
        int t = t0 + tid;
        int mode = g_maskmode;
        g_e[b * T + t] = read_mask(mask, b * T + t, mode) ? -INFINITY : s;
    }
}

// ---------------------------------------------------------------------------
// ctx_part + inline softmax: each block derives softmax norm from g_e (4 KB),
// computes its own 64-t weight slice, writes slice to out weights, and
// accumulates context partials. Kills the standalone softmax kernel.
// ---------------------------------------------------------------------------
__global__ void __launch_bounds__(256)
ctx_part_kernel(const float* __restrict__ key,
                float* __restrict__ out) {
    int b = blockIdx.y;
    int c = blockIdx.x;             // 0..15, 64 t each
    int tid = threadIdx.x;          // 256
    int e4 = tid & 127, h = tid >> 7;

    __shared__ float sred[256];
    __shared__ float ws[64];

    // ---- softmax normalization over full T (each block, redundant but tiny) ----
    float vals[4];
    float m = -INFINITY;
    #pragma unroll
    for (int i = 0; i < 4; i++) {
        vals[i] = g_e[b * T + tid + i * 256];
        m = fmaxf(m, vals[i]);
    }
    sred[tid] = m; __syncthreads();
    for (int s = 128; s > 0; s >>= 1) {
        if (tid < s) sred[tid] = fmaxf(sred[tid], sred[tid + s]);
        __syncthreads();
    }
    m = sred[0]; __syncthreads();

    float sum = 0.f;
    #pragma unroll
    for (int i = 0; i < 4; i++)
        sum += expf(vals[i] - m);
    sred[tid] = sum; __syncthreads();
    for (int s = 128; s > 0; s >>= 1) {
        if (tid < s) sred[tid] += sred[tid + s];
        __syncthreads();
    }
    float inv = 1.f / sred[0];
    __syncthreads();

    // ---- this block's 64-t weight slice ----
    if (tid < 64) {
        float w = expf(g_e[b * T + c * 64 + tid] - m) * inv;
        ws[tid] = w;
        out[B * E + (size_t)b * T + c * 64 + tid] = w;
    }
    __syncthreads();

    // ---- context partial over slice ----
    const float* w = ws + h * 32;
    const float4* kp = (const float4*)(key + (size_t)b * T * E)
                     + (size_t)(c * 64 + h * 32) * (E / 4) + e4;
    float4 acc = make_float4(0.f, 0.f, 0.f, 0.f);
    #pragma unroll 8
    for (int t = 0; t < 32; t++) {
        float4 k4 = kp[(size_t)t * (E / 4)];
        float wt = w[t];
        acc.x += wt * k4.x; acc.y += wt * k4.y;
        acc.z += wt * k4.z; acc.w += wt * k4.w;
    }
    __shared__ float4 sred4[256];
    sred4[tid] = acc;
    __syncthreads();
    if (h == 0) {
        float4 o = sred4[tid];
        float4 p = sred4[tid + 128];
        o.x += p.x; o.y += p.y; o.z += p.z; o.w += p.w;
        g_ctxpart4[(b * 16 + c) * (E / 4) + e4] = o;
    }
}

__global__ void ctx_reduce_kernel(float* __restrict__ out) {
    int b = blockIdx.x;
    int e4 = threadIdx.x;           // 128
    float4 s = make_float4(0.f, 0.f, 0.f, 0.f);
    #pragma unroll
    for (int c = 0; c < 16; c++) {
        float4 p = g_ctxpart4[(b * 16 + c) * (E / 4) + e4];
        s.x += p.x; s.y += p.y; s.z += p.z; s.w += p.w;
    }
    float* o = out + (size_t)b * E + e4 * 4;
    o[0] = s.x; o[1] = s.y; o[2] = s.z; o[3] = s.w;
}

// ---------------------------------------------------------------------------
extern "C" void kernel_launch(void* const* d_in, const int* in_sizes, int n_in,
                              void* d_out, int out_size) {
    const float* query  = (const float*)d_in[0];
    const float* key    = (const float*)d_in[1];
    const float* cat    = (const float*)d_in[2];
    const void*  mask   = (const void*)d_in[3];
    const float* Wq     = (const float*)d_in[4];
    const float* Wk     = (const float*)d_in[5];
    const float* conv_w = (const float*)d_in[6];
    const float* gamma  = (const float*)d_in[7];
    const float* beta   = (const float*)d_in[8];
    const float* mean   = (const float*)d_in[9];
    const float* var    = (const float*)d_in[10];
    const float* Wloc   = (const float*)d_in[11];
    const float* v      = (const float*)d_in[12];
    float* out = (float*)d_out;

    cudaFuncSetAttribute(energy_kernel,
                         cudaFuncAttributeMaxDynamicSharedMemorySize, SMEM_BYTES);

    prep_kernel<<<NB_PREP, 256>>>(query, Wq, cat, conv_w, gamma, beta, mean, var,
                                  Wk, Wloc, (const unsigned int*)mask);
    energy_kernel<<<dim3(T / TM, B), 256, SMEM_BYTES>>>(key, mask, v);
    ctx_part_kernel<<<dim3(16, B), 256>>>(key, out);
    ctx_reduce_kernel<<<B, 128>>>(out);
}